// round 10
// baseline (speedup 1.0000x reference)
#include <cuda_runtime.h>

#define N_NODES 100000
#define E_MSG   3200000
#define E_SC    1000000
#define IN_DIM  12
#define HID     64
#define EMB     32
#define EDGE_F  10
#define EDGE_REPR 74
#define D2PAD   80   // dec_W2 row padded to 2x40 halves

// ---------------- scratch (static device globals; no allocation) -------------
__device__ float g_agg1 [N_NODES * IN_DIM];
__device__ float g_cnt  [N_NODES];
__device__ float g_h    [N_NODES * HID];
__device__ float g_p    [N_NODES * EMB];   // h @ Wn2 (projected, 32-dim)
__device__ float g_agg2p[N_NODES * EMB];   // scatter of g_p
__device__ float g_emb  [N_NODES * EMB];

// ---------------- int32/int64 index handling ---------------------------------
__device__ __forceinline__ bool idx_is64(const void* p) {
    const int* q = (const int*)p;
    return (q[1] | q[3] | q[5]) == 0;
}
__device__ __forceinline__ long long ld_idx(const void* p, long long i, bool is64) {
    if (is64) return ((const long long*)p)[i];
    return (long long)((const int*)p)[i];
}

__device__ __forceinline__ float warp_sum(float v) {
#pragma unroll
    for (int o = 16; o > 0; o >>= 1) v += __shfl_xor_sync(0xffffffffu, v, o);
    return v;
}

// ---------------- packed f32x2 helpers (sm_100+) ------------------------------
__device__ __forceinline__ unsigned long long pk2(float a, float b) {
    unsigned long long r;
    asm("mov.b64 %0, {%1,%2};" : "=l"(r) : "f"(a), "f"(b));
    return r;
}
__device__ __forceinline__ void upk2(unsigned long long p, float& a, float& b) {
    asm("mov.b64 {%0,%1}, %2;" : "=f"(a), "=f"(b) : "l"(p));
}
__device__ __forceinline__ void fma2(unsigned long long& d,
                                     unsigned long long a, unsigned long long b) {
    asm("fma.rn.f32x2 %0, %1, %2, %0;" : "+l"(d) : "l"(a), "l"(b));
}

// ---------------- vector float atomic (sm_90+) --------------------------------
__device__ __forceinline__ void red_add_v4(float* addr, float4 v) {
    asm volatile("red.global.add.v4.f32 [%0], {%1,%2,%3,%4};"
                 :: "l"(addr), "f"(v.x), "f"(v.y), "f"(v.z), "f"(v.w) : "memory");
}

// ---------------- zero scratch ------------------------------------------------
__global__ __launch_bounds__(256) void zero_kernel() {
    int i = blockIdx.x * 256 + threadIdx.x;
    const int A1 = N_NODES * IN_DIM;            // 1.2M
    const int A2 = A1 + N_NODES;                // +0.1M
    const int A3 = A2 + N_NODES * EMB;          // +3.2M
    if (i < A1)      g_agg1[i] = 0.f;
    else if (i < A2) g_cnt[i - A1] = 0.f;
    else if (i < A3) g_agg2p[i - A2] = 0.f;
}

// ---------------- scatter layer-1 features + degree counts -------------------
__global__ __launch_bounds__(256) void scatter1_kernel(const void* __restrict__ ei,
                                                       const float* __restrict__ nf) {
    int e = blockIdx.x * 256 + threadIdx.x;
    if (e >= E_MSG) return;
    bool is64 = idx_is64(ei);
    long long s = ld_idx(ei, e, is64);
    long long d = ld_idx(ei, (long long)E_MSG + e, is64);
    const float4* x = (const float4*)(nf + s * IN_DIM);   // 48B rows, 16B aligned
    float* a = g_agg1 + d * IN_DIM;
#pragma unroll
    for (int j = 0; j < 3; j++) red_add_v4(a + 4 * j, x[j]);
    atomicAdd(g_cnt + d, 1.f);
}

// ---------------- SAGE layer 1: 12 -> 64 + LN + relu, fused proj h@Wn2 -------
__global__ __launch_bounds__(256) void sage1_kernel(const float* __restrict__ nf,
                                                    const float* __restrict__ Ws,
                                                    const float* __restrict__ Wn,
                                                    const float* __restrict__ b,
                                                    const float* __restrict__ g,
                                                    const float* __restrict__ be,
                                                    const float* __restrict__ Wn2) {
    __shared__ float sWs[IN_DIM * HID], sWn[IN_DIM * HID], sW2[HID * EMB];
    __shared__ float sb[HID], sg[HID], sbe[HID];
    for (int i = threadIdx.x; i < IN_DIM * HID; i += 256) { sWs[i] = Ws[i]; sWn[i] = Wn[i]; }
    for (int i = threadIdx.x; i < HID * EMB; i += 256) sW2[i] = Wn2[i];
    if (threadIdx.x < HID) {
        sb[threadIdx.x] = b[threadIdx.x];
        sg[threadIdx.x] = g[threadIdx.x];
        sbe[threadIdx.x] = be[threadIdx.x];
    }
    __syncthreads();
    int n = blockIdx.x * 8 + (threadIdx.x >> 5);
    int lane = threadIdx.x & 31;
    float inv = 1.f / fmaxf(g_cnt[n], 1.f);
    float h0 = sb[lane], h1 = sb[lane + 32];
#pragma unroll
    for (int k = 0; k < IN_DIM; k++) {
        float xk = nf[n * IN_DIM + k];
        float ak = g_agg1[n * IN_DIM + k] * inv;
        h0 += xk * sWs[k * HID + lane]      + ak * sWn[k * HID + lane];
        h1 += xk * sWs[k * HID + lane + 32] + ak * sWn[k * HID + lane + 32];
    }
    float s1 = warp_sum(h0 + h1);
    float s2 = warp_sum(h0 * h0 + h1 * h1);
    float mu  = s1 * (1.f / 64.f);
    float var = s2 * (1.f / 64.f) - mu * mu;
    float r = rsqrtf(var + 1e-5f);
    float o0 = fmaxf((h0 - mu) * r * sg[lane]      + sbe[lane],      0.f);
    float o1 = fmaxf((h1 - mu) * r * sg[lane + 32] + sbe[lane + 32], 0.f);
    g_h[n * HID + lane]      = o0;
    g_h[n * HID + lane + 32] = o1;
    // fused projection: p = h @ Wn2 (h is lane-distributed in o0/o1)
    float acc = 0.f;
#pragma unroll
    for (int k = 0; k < 32; k++)
        acc += __shfl_sync(0xffffffffu, o0, k) * sW2[k * EMB + lane];
#pragma unroll
    for (int k = 0; k < 32; k++)
        acc += __shfl_sync(0xffffffffu, o1, k) * sW2[(k + 32) * EMB + lane];
    g_p[n * EMB + lane] = acc;
}

// ---------------- scatter layer-2 (projected): p[src] -> agg2p[dst] ----------
__global__ __launch_bounds__(256) void scatter2_kernel(const void* __restrict__ ei) {
    int e = blockIdx.x * 256 + threadIdx.x;
    if (e >= E_MSG) return;
    bool is64 = idx_is64(ei);
    long long s = ld_idx(ei, e, is64);
    long long d = ld_idx(ei, (long long)E_MSG + e, is64);
    const float4* ps = (const float4*)(g_p + s * EMB);    // 128B rows
    float* pd = g_agg2p + d * EMB;
#pragma unroll
    for (int j = 0; j < 8; j++) red_add_v4(pd + 4 * j, ps[j]);
}

// ---------------- SAGE layer 2: 64 -> 32 + LN + relu -------------------------
__global__ __launch_bounds__(256) void sage2_kernel(const float* __restrict__ Ws,
                                                    const float* __restrict__ b,
                                                    const float* __restrict__ g,
                                                    const float* __restrict__ be) {
    __shared__ float sWs[HID * EMB];
    __shared__ float sb[EMB], sg[EMB], sbe[EMB];
    for (int i = threadIdx.x; i < HID * EMB; i += 256) sWs[i] = Ws[i];
    if (threadIdx.x < EMB) {
        sb[threadIdx.x] = b[threadIdx.x];
        sg[threadIdx.x] = g[threadIdx.x];
        sbe[threadIdx.x] = be[threadIdx.x];
    }
    __syncthreads();
    int n = blockIdx.x * 8 + (threadIdx.x >> 5);
    int lane = threadIdx.x & 31;
    float inv = 1.f / fmaxf(g_cnt[n], 1.f);
    float hl = g_h[n * HID + lane];
    float hh = g_h[n * HID + 32 + lane];
    float acc = sb[lane] + g_agg2p[n * EMB + lane] * inv;
#pragma unroll
    for (int k = 0; k < 32; k++)
        acc += __shfl_sync(0xffffffffu, hl, k) * sWs[k * EMB + lane];
#pragma unroll
    for (int k = 0; k < 32; k++)
        acc += __shfl_sync(0xffffffffu, hh, k) * sWs[(k + 32) * EMB + lane];
    float s1 = warp_sum(acc);
    float s2 = warp_sum(acc * acc);
    float mu  = s1 * (1.f / 32.f);
    float var = s2 * (1.f / 32.f) - mu * mu;
    float r = rsqrtf(var + 1e-5f);
    g_emb[n * EMB + lane] = fmaxf((acc - mu) * r * sg[lane] + sbe[lane], 0.f);
}

// ---------------- fused edge_rep + edge MLP (packed f32x2, streaming) --------
// Shared layout (floats): W1(74*64) W2(64*32) D1(32*64) D2(64*80) b1(64) b2(32) b3(64) b4(80)
#define SM_W1 0
#define SM_W2 (SM_W1 + EDGE_REPR * HID)
#define SM_D1 (SM_W2 + HID * EMB)
#define SM_D2 (SM_D1 + EMB * HID)
#define SM_B1 (SM_D2 + HID * D2PAD)
#define SM_B2 (SM_B1 + HID)
#define SM_B3 (SM_B2 + EMB)
#define SM_B4 (SM_B3 + HID)
#define SM_TOTAL (SM_B4 + D2PAD)   // 14192 floats = 56768 B

#define MLP_THREADS 128

// sweep one input element (broadcast pair m) against a 64-wide weight row into a1[32]
#define SWEEP64(acc, m, rowptr)                                            \
    {                                                                      \
        const ulonglong2* _w = (const ulonglong2*)(rowptr);                \
        _Pragma("unroll")                                                  \
        for (int _jj = 0; _jj < 16; _jj++) {                               \
            ulonglong2 _t = _w[_jj];                                       \
            fma2((acc)[2 * _jj], (m), _t.x);                               \
            fma2((acc)[2 * _jj + 1], (m), _t.y);                           \
        }                                                                  \
    }

__global__ __launch_bounds__(MLP_THREADS, 4) void edge_mlp_kernel(
    const void* __restrict__ srcn, const void* __restrict__ dstn,
    const float* __restrict__ ea,
    const float* __restrict__ eW1, const float* __restrict__ eb1,
    const float* __restrict__ eW2, const float* __restrict__ eb2,
    const float* __restrict__ dW1, const float* __restrict__ db1,
    const float* __restrict__ dW2, const float* __restrict__ db2,
    float* __restrict__ out_recon, float* __restrict__ out_er) {
    extern __shared__ float sm[];
    for (int i = threadIdx.x; i < EDGE_REPR * HID; i += MLP_THREADS) sm[SM_W1 + i] = eW1[i];
    for (int i = threadIdx.x; i < HID * EMB; i += MLP_THREADS)       sm[SM_W2 + i] = eW2[i];
    for (int i = threadIdx.x; i < EMB * HID; i += MLP_THREADS)       sm[SM_D1 + i] = dW1[i];
    for (int i = threadIdx.x; i < HID * D2PAD; i += MLP_THREADS) {
        int k = i / D2PAD, j = i - k * D2PAD;
        sm[SM_D2 + i] = (j < EDGE_REPR) ? dW2[k * EDGE_REPR + j] : 0.f;
    }
    for (int i = threadIdx.x; i < HID; i += MLP_THREADS) { sm[SM_B1 + i] = eb1[i]; sm[SM_B3 + i] = db1[i]; }
    for (int i = threadIdx.x; i < EMB; i += MLP_THREADS)   sm[SM_B2 + i] = eb2[i];
    for (int i = threadIdx.x; i < D2PAD; i += MLP_THREADS) sm[SM_B4 + i] = (i < EDGE_REPR) ? db2[i] : 0.f;
    __syncthreads();

    int e = blockIdx.x * MLP_THREADS + threadIdx.x;
    if (e >= E_SC) return;
    bool is64s = idx_is64(srcn);
    bool is64d = idx_is64(dstn);
    long long s = ld_idx(srcn, e, is64s);
    long long d = ld_idx(dstn, e, is64d);

    unsigned long long* o_er = (unsigned long long*)(out_er + (long long)e * EDGE_REPR);

    // -------- enc1 (streaming): a1 = er @ W1 + b1; er chunks also written to out_er
    unsigned long long a1[HID / 2];
    {
        const unsigned long long* bp = (const unsigned long long*)(sm + SM_B1);
#pragma unroll
        for (int j = 0; j < HID / 2; j++) a1[j] = bp[j];
    }
    {
        const float4* es = (const float4*)(g_emb + s * EMB);
#pragma unroll
        for (int c = 0; c < 8; c++) {
            float4 v = es[c];
            o_er[2 * c]     = pk2(v.x, v.y);
            o_er[2 * c + 1] = pk2(v.z, v.w);
            int k = 4 * c;
            SWEEP64(a1, pk2(v.x, v.x), sm + SM_W1 + (k + 0) * HID);
            SWEEP64(a1, pk2(v.y, v.y), sm + SM_W1 + (k + 1) * HID);
            SWEEP64(a1, pk2(v.z, v.z), sm + SM_W1 + (k + 2) * HID);
            SWEEP64(a1, pk2(v.w, v.w), sm + SM_W1 + (k + 3) * HID);
        }
        const float4* ed = (const float4*)(g_emb + d * EMB);
#pragma unroll
        for (int c = 0; c < 8; c++) {
            float4 v = ed[c];
            o_er[16 + 2 * c]     = pk2(v.x, v.y);
            o_er[16 + 2 * c + 1] = pk2(v.z, v.w);
            int k = EMB + 4 * c;
            SWEEP64(a1, pk2(v.x, v.x), sm + SM_W1 + (k + 0) * HID);
            SWEEP64(a1, pk2(v.y, v.y), sm + SM_W1 + (k + 1) * HID);
            SWEEP64(a1, pk2(v.z, v.z), sm + SM_W1 + (k + 2) * HID);
            SWEEP64(a1, pk2(v.w, v.w), sm + SM_W1 + (k + 3) * HID);
        }
#pragma unroll
        for (int c = 0; c < EDGE_F / 2; c++) {
            float f0 = ea[(long long)e * EDGE_F + 2 * c];
            float f1 = ea[(long long)e * EDGE_F + 2 * c + 1];
            o_er[32 + c] = pk2(f0, f1);
            int k = 2 * EMB + 2 * c;
            SWEEP64(a1, pk2(f0, f0), sm + SM_W1 + (k + 0) * HID);
            SWEEP64(a1, pk2(f1, f1), sm + SM_W1 + (k + 1) * HID);
        }
    }

    // -------- enc2: 64 -> 32, relu applied to a1 on the fly --------
    unsigned long long a2[EMB / 2];
    {
        const unsigned long long* bp = (const unsigned long long*)(sm + SM_B2);
#pragma unroll
        for (int j = 0; j < EMB / 2; j++) a2[j] = bp[j];
#pragma unroll
        for (int kp = 0; kp < HID / 2; kp++) {
            float f0, f1;
            upk2(a1[kp], f0, f1);
            f0 = fmaxf(f0, 0.f);
            f1 = fmaxf(f1, 0.f);
            unsigned long long m0 = pk2(f0, f0);
            unsigned long long m1 = pk2(f1, f1);
            const ulonglong2* w0 = (const ulonglong2*)(sm + SM_W2 + (2 * kp) * EMB);
            const ulonglong2* w1 = (const ulonglong2*)(sm + SM_W2 + (2 * kp + 1) * EMB);
#pragma unroll
            for (int jj = 0; jj < 8; jj++) {
                ulonglong2 t0 = w0[jj];
                fma2(a2[2 * jj], m0, t0.x);
                fma2(a2[2 * jj + 1], m0, t0.y);
            }
#pragma unroll
            for (int jj = 0; jj < 8; jj++) {
                ulonglong2 t1 = w1[jj];
                fma2(a2[2 * jj], m1, t1.x);
                fma2(a2[2 * jj + 1], m1, t1.y);
            }
        }
    }

    // -------- dec1: 32 -> 64 (relu on a2 on the fly), result in a3 --------
    unsigned long long a3[HID / 2];
    {
        const unsigned long long* bp = (const unsigned long long*)(sm + SM_B3);
#pragma unroll
        for (int j = 0; j < HID / 2; j++) a3[j] = bp[j];
#pragma unroll
        for (int kp = 0; kp < EMB / 2; kp++) {
            float f0, f1;
            upk2(a2[kp], f0, f1);
            f0 = fmaxf(f0, 0.f);
            f1 = fmaxf(f1, 0.f);
            SWEEP64(a3, pk2(f0, f0), sm + SM_D1 + (2 * kp) * HID);
            SWEEP64(a3, pk2(f1, f1), sm + SM_D1 + (2 * kp + 1) * HID);
        }
    }
    // relu a3 in place (h2)
#pragma unroll
    for (int j = 0; j < HID / 2; j++) {
        float f0, f1;
        upk2(a3[j], f0, f1);
        a3[j] = pk2(fmaxf(f0, 0.f), fmaxf(f1, 0.f));
    }

    // -------- dec2: 64 -> 74 in two 40-column halves --------
    unsigned long long* o = (unsigned long long*)(out_recon + (long long)e * EDGE_REPR);
#pragma unroll
    for (int h = 0; h < 2; h++) {
        unsigned long long a4[20];
        const unsigned long long* bp = (const unsigned long long*)(sm + SM_B4 + h * 40);
#pragma unroll
        for (int j = 0; j < 20; j++) a4[j] = bp[j];
#pragma unroll
        for (int kp = 0; kp < HID / 2; kp++) {
            float f0, f1;
            upk2(a3[kp], f0, f1);
            unsigned long long m0 = pk2(f0, f0);
            unsigned long long m1 = pk2(f1, f1);
            const ulonglong2* w0 = (const ulonglong2*)(sm + SM_D2 + (2 * kp) * D2PAD + h * 40);
            const ulonglong2* w1 = (const ulonglong2*)(sm + SM_D2 + (2 * kp + 1) * D2PAD + h * 40);
#pragma unroll
            for (int jj = 0; jj < 10; jj++) {
                ulonglong2 t0 = w0[jj];
                fma2(a4[2 * jj], m0, t0.x);
                fma2(a4[2 * jj + 1], m0, t0.y);
            }
#pragma unroll
            for (int jj = 0; jj < 10; jj++) {
                ulonglong2 t1 = w1[jj];
                fma2(a4[2 * jj], m1, t1.x);
                fma2(a4[2 * jj + 1], m1, t1.y);
            }
        }
        if (h == 0) {
#pragma unroll
            for (int j = 0; j < 20; j++) o[j] = a4[j];        // cols 0..39
        } else {
#pragma unroll
            for (int j = 0; j < 17; j++) o[20 + j] = a4[j];   // cols 40..73
        }
    }
}

// ---------------- launcher ----------------------------------------------------
extern "C" void kernel_launch(void* const* d_in, const int* in_sizes, int n_in,
                              void* d_out, int out_size) {
    const float* nf   = (const float*)d_in[0];
    const void*  ei   = d_in[1];
    const float* ea   = (const float*)d_in[2];
    const void*  srcn = d_in[3];
    const void*  dstn = d_in[4];
    const float* Ws1 = (const float*)d_in[5];
    const float* Wn1 = (const float*)d_in[6];
    const float* b1  = (const float*)d_in[7];
    const float* g1  = (const float*)d_in[8];
    const float* be1 = (const float*)d_in[9];
    const float* Ws2 = (const float*)d_in[10];
    const float* Wn2 = (const float*)d_in[11];
    const float* b2  = (const float*)d_in[12];
    const float* g2  = (const float*)d_in[13];
    const float* be2 = (const float*)d_in[14];
    const float* eW1 = (const float*)d_in[15];
    const float* eb1 = (const float*)d_in[16];
    const float* eW2 = (const float*)d_in[17];
    const float* eb2 = (const float*)d_in[18];
    const float* dW1 = (const float*)d_in[19];
    const float* db1 = (const float*)d_in[20];
    const float* dW2 = (const float*)d_in[21];
    const float* db2 = (const float*)d_in[22];

    float* out_recon = (float*)d_out;                                   // [1M, 74]
    float* out_er    = (float*)d_out + (long long)E_SC * EDGE_REPR;     // [1M, 74]

    const int smem_mlp = SM_TOTAL * sizeof(float);  // 56768 B
    cudaFuncSetAttribute(edge_mlp_kernel, cudaFuncAttributeMaxDynamicSharedMemorySize, smem_mlp);

    const int zero_total = N_NODES * IN_DIM + N_NODES + N_NODES * EMB;
    zero_kernel<<<(zero_total + 255) / 256, 256>>>();
    scatter1_kernel<<<(E_MSG + 255) / 256, 256>>>(ei, nf);
    sage1_kernel<<<N_NODES / 8, 256>>>(nf, Ws1, Wn1, b1, g1, be1, Wn2);
    scatter2_kernel<<<(E_MSG + 255) / 256, 256>>>(ei);
    sage2_kernel<<<N_NODES / 8, 256>>>(Ws2, b2, g2, be2);
    edge_mlp_kernel<<<(E_SC + MLP_THREADS - 1) / MLP_THREADS, MLP_THREADS, smem_mlp>>>(
        srcn, dstn, ea, eW1, eb1, eW2, eb2, dW1, db1, dW2, db2, out_recon, out_er);
}

// round 11
// speedup vs baseline: 1.3946x; 1.3946x over previous
#include <cuda_runtime.h>

#define N_NODES 100000
#define E_MSG   3200000
#define E_SC    1000000
#define IN_DIM  12
#define HID     64
#define EMB     32
#define EDGE_F  10
#define EDGE_REPR 74
#define D2PAD   80   // dec_W2 row padded to 2x40 halves

// ---------------- scratch (static device globals; no allocation) -------------
__device__ float g_agg1 [N_NODES * IN_DIM];
__device__ float g_cnt  [N_NODES];
__device__ float g_h    [N_NODES * HID];
__device__ float g_p    [N_NODES * EMB];   // h @ Wn2 (projected, 32-dim)
__device__ float g_agg2p[N_NODES * EMB];   // scatter of g_p
__device__ float g_emb  [N_NODES * EMB];

// ---------------- int32/int64 index handling ---------------------------------
__device__ __forceinline__ bool idx_is64(const void* p) {
    const int* q = (const int*)p;
    return (q[1] | q[3] | q[5]) == 0;
}
__device__ __forceinline__ long long ld_idx(const void* p, long long i, bool is64) {
    if (is64) return ((const long long*)p)[i];
    return (long long)((const int*)p)[i];
}

__device__ __forceinline__ float warp_sum(float v) {
#pragma unroll
    for (int o = 16; o > 0; o >>= 1) v += __shfl_xor_sync(0xffffffffu, v, o);
    return v;
}

// ---------------- packed f32x2 helpers (sm_100+) ------------------------------
__device__ __forceinline__ unsigned long long pk2(float a, float b) {
    unsigned long long r;
    asm("mov.b64 %0, {%1,%2};" : "=l"(r) : "f"(a), "f"(b));
    return r;
}
__device__ __forceinline__ void upk2(unsigned long long p, float& a, float& b) {
    asm("mov.b64 {%0,%1}, %2;" : "=f"(a), "=f"(b) : "l"(p));
}
__device__ __forceinline__ void fma2(unsigned long long& d,
                                     unsigned long long a, unsigned long long b) {
    asm("fma.rn.f32x2 %0, %1, %2, %0;" : "+l"(d) : "l"(a), "l"(b));
}
// width-2 shuffle of a 64-bit value (src is 0 or 1 within the pair)
__device__ __forceinline__ unsigned long long shfl64p(unsigned long long v, int src) {
    unsigned int lo = (unsigned int)v, hi = (unsigned int)(v >> 32);
    lo = __shfl_sync(0xffffffffu, lo, src, 2);
    hi = __shfl_sync(0xffffffffu, hi, src, 2);
    return ((unsigned long long)hi << 32) | lo;
}

// ---------------- vector float atomic (sm_90+) --------------------------------
__device__ __forceinline__ void red_add_v4(float* addr, float4 v) {
    asm volatile("red.global.add.v4.f32 [%0], {%1,%2,%3,%4};"
                 :: "l"(addr), "f"(v.x), "f"(v.y), "f"(v.z), "f"(v.w) : "memory");
}

// ---------------- zero scratch ------------------------------------------------
__global__ __launch_bounds__(256) void zero_kernel() {
    int i = blockIdx.x * 256 + threadIdx.x;
    const int A1 = N_NODES * IN_DIM;            // 1.2M
    const int A2 = A1 + N_NODES;                // +0.1M
    const int A3 = A2 + N_NODES * EMB;          // +3.2M
    if (i < A1)      g_agg1[i] = 0.f;
    else if (i < A2) g_cnt[i - A1] = 0.f;
    else if (i < A3) g_agg2p[i - A2] = 0.f;
}

// ---------------- scatter layer-1 features + degree counts -------------------
__global__ __launch_bounds__(256) void scatter1_kernel(const void* __restrict__ ei,
                                                       const float* __restrict__ nf) {
    int e = blockIdx.x * 256 + threadIdx.x;
    if (e >= E_MSG) return;
    bool is64 = idx_is64(ei);
    long long s = ld_idx(ei, e, is64);
    long long d = ld_idx(ei, (long long)E_MSG + e, is64);
    const float4* x = (const float4*)(nf + s * IN_DIM);   // 48B rows, 16B aligned
    float* a = g_agg1 + d * IN_DIM;
#pragma unroll
    for (int j = 0; j < 3; j++) red_add_v4(a + 4 * j, x[j]);
    atomicAdd(g_cnt + d, 1.f);
}

// ---------------- SAGE layer 1: 12 -> 64 + LN + relu, fused proj h@Wn2 -------
__global__ __launch_bounds__(256) void sage1_kernel(const float* __restrict__ nf,
                                                    const float* __restrict__ Ws,
                                                    const float* __restrict__ Wn,
                                                    const float* __restrict__ b,
                                                    const float* __restrict__ g,
                                                    const float* __restrict__ be,
                                                    const float* __restrict__ Wn2) {
    __shared__ float sWs[IN_DIM * HID], sWn[IN_DIM * HID], sW2[HID * EMB];
    __shared__ float sb[HID], sg[HID], sbe[HID];
    for (int i = threadIdx.x; i < IN_DIM * HID; i += 256) { sWs[i] = Ws[i]; sWn[i] = Wn[i]; }
    for (int i = threadIdx.x; i < HID * EMB; i += 256) sW2[i] = Wn2[i];
    if (threadIdx.x < HID) {
        sb[threadIdx.x] = b[threadIdx.x];
        sg[threadIdx.x] = g[threadIdx.x];
        sbe[threadIdx.x] = be[threadIdx.x];
    }
    __syncthreads();
    int n = blockIdx.x * 8 + (threadIdx.x >> 5);
    int lane = threadIdx.x & 31;
    float inv = 1.f / fmaxf(g_cnt[n], 1.f);
    float h0 = sb[lane], h1 = sb[lane + 32];
#pragma unroll
    for (int k = 0; k < IN_DIM; k++) {
        float xk = nf[n * IN_DIM + k];
        float ak = g_agg1[n * IN_DIM + k] * inv;
        h0 += xk * sWs[k * HID + lane]      + ak * sWn[k * HID + lane];
        h1 += xk * sWs[k * HID + lane + 32] + ak * sWn[k * HID + lane + 32];
    }
    float s1 = warp_sum(h0 + h1);
    float s2 = warp_sum(h0 * h0 + h1 * h1);
    float mu  = s1 * (1.f / 64.f);
    float var = s2 * (1.f / 64.f) - mu * mu;
    float r = rsqrtf(var + 1e-5f);
    float o0 = fmaxf((h0 - mu) * r * sg[lane]      + sbe[lane],      0.f);
    float o1 = fmaxf((h1 - mu) * r * sg[lane + 32] + sbe[lane + 32], 0.f);
    g_h[n * HID + lane]      = o0;
    g_h[n * HID + lane + 32] = o1;
    // fused projection: p = h @ Wn2 (h is lane-distributed in o0/o1)
    float acc = 0.f;
#pragma unroll
    for (int k = 0; k < 32; k++)
        acc += __shfl_sync(0xffffffffu, o0, k) * sW2[k * EMB + lane];
#pragma unroll
    for (int k = 0; k < 32; k++)
        acc += __shfl_sync(0xffffffffu, o1, k) * sW2[(k + 32) * EMB + lane];
    g_p[n * EMB + lane] = acc;
}

// ---------------- scatter layer-2 (projected): p[src] -> agg2p[dst] ----------
__global__ __launch_bounds__(256) void scatter2_kernel(const void* __restrict__ ei) {
    int e = blockIdx.x * 256 + threadIdx.x;
    if (e >= E_MSG) return;
    bool is64 = idx_is64(ei);
    long long s = ld_idx(ei, e, is64);
    long long d = ld_idx(ei, (long long)E_MSG + e, is64);
    const float4* ps = (const float4*)(g_p + s * EMB);    // 128B rows
    float* pd = g_agg2p + d * EMB;
#pragma unroll
    for (int j = 0; j < 8; j++) red_add_v4(pd + 4 * j, ps[j]);
}

// ---------------- SAGE layer 2: 64 -> 32 + LN + relu -------------------------
__global__ __launch_bounds__(256) void sage2_kernel(const float* __restrict__ Ws,
                                                    const float* __restrict__ b,
                                                    const float* __restrict__ g,
                                                    const float* __restrict__ be) {
    __shared__ float sWs[HID * EMB];
    __shared__ float sb[EMB], sg[EMB], sbe[EMB];
    for (int i = threadIdx.x; i < HID * EMB; i += 256) sWs[i] = Ws[i];
    if (threadIdx.x < EMB) {
        sb[threadIdx.x] = b[threadIdx.x];
        sg[threadIdx.x] = g[threadIdx.x];
        sbe[threadIdx.x] = be[threadIdx.x];
    }
    __syncthreads();
    int n = blockIdx.x * 8 + (threadIdx.x >> 5);
    int lane = threadIdx.x & 31;
    float inv = 1.f / fmaxf(g_cnt[n], 1.f);
    float hl = g_h[n * HID + lane];
    float hh = g_h[n * HID + 32 + lane];
    float acc = sb[lane] + g_agg2p[n * EMB + lane] * inv;
#pragma unroll
    for (int k = 0; k < 32; k++)
        acc += __shfl_sync(0xffffffffu, hl, k) * sWs[k * EMB + lane];
#pragma unroll
    for (int k = 0; k < 32; k++)
        acc += __shfl_sync(0xffffffffu, hh, k) * sWs[(k + 32) * EMB + lane];
    float s1 = warp_sum(acc);
    float s2 = warp_sum(acc * acc);
    float mu  = s1 * (1.f / 32.f);
    float var = s2 * (1.f / 32.f) - mu * mu;
    float r = rsqrtf(var + 1e-5f);
    g_emb[n * EMB + lane] = fmaxf((acc - mu) * r * sg[lane] + sbe[lane], 0.f);
}

// ---------------- fused edge_rep + edge MLP: 2 threads per edge --------------
// Each pair of threads (2i, 2i+1) handles one edge. Thread `half` owns the
// columns [half*W/2, (half+1)*W/2) of every layer output. Inputs cross the
// pair via width-2 shuffles with static register indices.
// Shared layout (floats): W1(74*64) W2(64*32) D1(32*64) D2(64*80) b1(64) b2(32) b3(64) b4(80)
#define SM_W1 0
#define SM_W2 (SM_W1 + EDGE_REPR * HID)
#define SM_D1 (SM_W2 + HID * EMB)
#define SM_D2 (SM_D1 + EMB * HID)
#define SM_B1 (SM_D2 + HID * D2PAD)
#define SM_B2 (SM_B1 + HID)
#define SM_B3 (SM_B2 + EMB)
#define SM_B4 (SM_B3 + HID)
#define SM_TOTAL (SM_B4 + D2PAD)   // 14192 floats = 56768 B

#define MLP_THREADS 256
#define EDGES_PER_BLOCK 128

__global__ __launch_bounds__(MLP_THREADS, 2) void edge_mlp_kernel(
    const void* __restrict__ srcn, const void* __restrict__ dstn,
    const float* __restrict__ ea,
    const float* __restrict__ eW1, const float* __restrict__ eb1,
    const float* __restrict__ eW2, const float* __restrict__ eb2,
    const float* __restrict__ dW1, const float* __restrict__ db1,
    const float* __restrict__ dW2, const float* __restrict__ db2,
    float* __restrict__ out_recon, float* __restrict__ out_er) {
    extern __shared__ float sm[];
    for (int i = threadIdx.x; i < EDGE_REPR * HID; i += MLP_THREADS) sm[SM_W1 + i] = eW1[i];
    for (int i = threadIdx.x; i < HID * EMB; i += MLP_THREADS)       sm[SM_W2 + i] = eW2[i];
    for (int i = threadIdx.x; i < EMB * HID; i += MLP_THREADS)       sm[SM_D1 + i] = dW1[i];
    for (int i = threadIdx.x; i < HID * D2PAD; i += MLP_THREADS) {
        int k = i / D2PAD, j = i - k * D2PAD;
        sm[SM_D2 + i] = (j < EDGE_REPR) ? dW2[k * EDGE_REPR + j] : 0.f;
    }
    for (int i = threadIdx.x; i < HID; i += MLP_THREADS) { sm[SM_B1 + i] = eb1[i]; sm[SM_B3 + i] = db1[i]; }
    for (int i = threadIdx.x; i < EMB; i += MLP_THREADS)   sm[SM_B2 + i] = eb2[i];
    for (int i = threadIdx.x; i < D2PAD; i += MLP_THREADS) sm[SM_B4 + i] = (i < EDGE_REPR) ? db2[i] : 0.f;
    __syncthreads();

    int half = threadIdx.x & 1;
    int e = blockIdx.x * EDGES_PER_BLOCK + (threadIdx.x >> 1);
    bool active = (e < E_SC);
    if (!active) e = 0;                 // keep warp lanes resident for shuffles
    bool is64s = idx_is64(srcn);
    bool is64d = idx_is64(dstn);
    long long node = half ? ld_idx(dstn, e, is64d) : ld_idx(srcn, e, is64s);

    // -------- gather: my_er[0..31] = emb[node]; my_er[32..41] = edge_attr ----
    float my_er[42];
    {
        const float4* rp = (const float4*)(g_emb + node * EMB);
#pragma unroll
        for (int j = 0; j < 8; j++) {
            float4 v = rp[j];
            my_er[4 * j] = v.x; my_er[4 * j + 1] = v.y;
            my_er[4 * j + 2] = v.z; my_er[4 * j + 3] = v.w;
        }
#pragma unroll
        for (int i = 0; i < EDGE_F; i++) my_er[EMB + i] = ea[(long long)e * EDGE_F + i];
    }
    // write edge_rep: thread0 -> cols 0..31, thread1 -> cols 32..73
    if (active) {
        unsigned long long* o = (unsigned long long*)(out_er + (long long)e * EDGE_REPR);
#pragma unroll
        for (int j = 0; j < 16; j++)
            o[16 * half + j] = pk2(my_er[2 * j], my_er[2 * j + 1]);
        if (half) {
#pragma unroll
            for (int j = 0; j < EDGE_F / 2; j++)
                o[32 + j] = pk2(my_er[EMB + 2 * j], my_er[EMB + 2 * j + 1]);
        }
    }

    // -------- enc1: 74 -> 64; thread owns output cols [32h, 32h+32) ----------
    unsigned long long a1[16];
    {
        const unsigned long long* bp = (const unsigned long long*)(sm + SM_B1 + 32 * half);
#pragma unroll
        for (int j = 0; j < 16; j++) a1[j] = bp[j];
#pragma unroll
        for (int k = 0; k < EDGE_REPR; k++) {
            float ek = (k < EMB)
                ? __shfl_sync(0xffffffffu, my_er[k < EMB ? k : 0], 0, 2)
                : __shfl_sync(0xffffffffu, my_er[k >= EMB ? k - EMB : 0], 1, 2);
            unsigned long long m = pk2(ek, ek);
            const ulonglong2* w = (const ulonglong2*)(sm + SM_W1 + k * HID + 32 * half);
#pragma unroll
            for (int jj = 0; jj < 8; jj++) {
                ulonglong2 t = w[jj];
                fma2(a1[2 * jj], m, t.x);
                fma2(a1[2 * jj + 1], m, t.y);
            }
        }
        // relu in place
#pragma unroll
        for (int j = 0; j < 16; j++) {
            float f0, f1;
            upk2(a1[j], f0, f1);
            a1[j] = pk2(fmaxf(f0, 0.f), fmaxf(f1, 0.f));
        }
    }

    // -------- enc2: 64 -> 32; thread owns output cols [16h, 16h+16) ----------
    unsigned long long a2[8];
    {
        const unsigned long long* bp = (const unsigned long long*)(sm + SM_B2 + 16 * half);
#pragma unroll
        for (int j = 0; j < 8; j++) a2[j] = bp[j];
#pragma unroll
        for (int kp = 0; kp < 32; kp++) {            // global r1 pair index
            unsigned long long v = shfl64p(a1[kp & 15], kp >> 4);
            float f0, f1;
            upk2(v, f0, f1);
            unsigned long long m0 = pk2(f0, f0);
            unsigned long long m1 = pk2(f1, f1);
            const ulonglong2* w0 = (const ulonglong2*)(sm + SM_W2 + (2 * kp) * EMB + 16 * half);
            const ulonglong2* w1 = (const ulonglong2*)(sm + SM_W2 + (2 * kp + 1) * EMB + 16 * half);
#pragma unroll
            for (int jj = 0; jj < 4; jj++) {
                ulonglong2 t = w0[jj];
                fma2(a2[2 * jj], m0, t.x);
                fma2(a2[2 * jj + 1], m0, t.y);
            }
#pragma unroll
            for (int jj = 0; jj < 4; jj++) {
                ulonglong2 t = w1[jj];
                fma2(a2[2 * jj], m1, t.x);
                fma2(a2[2 * jj + 1], m1, t.y);
            }
        }
        // relu in place
#pragma unroll
        for (int j = 0; j < 8; j++) {
            float f0, f1;
            upk2(a2[j], f0, f1);
            a2[j] = pk2(fmaxf(f0, 0.f), fmaxf(f1, 0.f));
        }
    }

    // -------- dec1: 32 -> 64; thread owns output cols [32h, 32h+32) ----------
    unsigned long long a3[16];
    {
        const unsigned long long* bp = (const unsigned long long*)(sm + SM_B3 + 32 * half);
#pragma unroll
        for (int j = 0; j < 16; j++) a3[j] = bp[j];
#pragma unroll
        for (int kp = 0; kp < 16; kp++) {            // global lat pair index
            unsigned long long v = shfl64p(a2[kp & 7], kp >> 3);
            float f0, f1;
            upk2(v, f0, f1);
            unsigned long long m0 = pk2(f0, f0);
            unsigned long long m1 = pk2(f1, f1);
            const ulonglong2* w0 = (const ulonglong2*)(sm + SM_D1 + (2 * kp) * HID + 32 * half);
            const ulonglong2* w1 = (const ulonglong2*)(sm + SM_D1 + (2 * kp + 1) * HID + 32 * half);
#pragma unroll
            for (int jj = 0; jj < 8; jj++) {
                ulonglong2 t = w0[jj];
                fma2(a3[2 * jj], m0, t.x);
                fma2(a3[2 * jj + 1], m0, t.y);
            }
#pragma unroll
            for (int jj = 0; jj < 8; jj++) {
                ulonglong2 t = w1[jj];
                fma2(a3[2 * jj], m1, t.x);
                fma2(a3[2 * jj + 1], m1, t.y);
            }
        }
        // relu in place (h2)
#pragma unroll
        for (int j = 0; j < 16; j++) {
            float f0, f1;
            upk2(a3[j], f0, f1);
            a3[j] = pk2(fmaxf(f0, 0.f), fmaxf(f1, 0.f));
        }
    }

    // -------- dec2: 64 -> 74 (padded 80); thread owns cols [40h, 40h+40) -----
    unsigned long long a4[20];
    {
        const unsigned long long* bp = (const unsigned long long*)(sm + SM_B4 + 40 * half);
#pragma unroll
        for (int j = 0; j < 20; j++) a4[j] = bp[j];
#pragma unroll
        for (int kp = 0; kp < 32; kp++) {            // global h2 pair index
            unsigned long long v = shfl64p(a3[kp & 15], kp >> 4);
            float f0, f1;
            upk2(v, f0, f1);
            unsigned long long m0 = pk2(f0, f0);
            unsigned long long m1 = pk2(f1, f1);
            const ulonglong2* w0 = (const ulonglong2*)(sm + SM_D2 + (2 * kp) * D2PAD + 40 * half);
            const ulonglong2* w1 = (const ulonglong2*)(sm + SM_D2 + (2 * kp + 1) * D2PAD + 40 * half);
#pragma unroll
            for (int jj = 0; jj < 10; jj++) {
                ulonglong2 t = w0[jj];
                fma2(a4[2 * jj], m0, t.x);
                fma2(a4[2 * jj + 1], m0, t.y);
            }
#pragma unroll
            for (int jj = 0; jj < 10; jj++) {
                ulonglong2 t = w1[jj];
                fma2(a4[2 * jj], m1, t.x);
                fma2(a4[2 * jj + 1], m1, t.y);
            }
        }
    }
    if (active) {
        unsigned long long* o = (unsigned long long*)(out_recon + (long long)e * EDGE_REPR);
        if (half == 0) {
#pragma unroll
            for (int j = 0; j < 20; j++) o[j] = a4[j];        // cols 0..39
        } else {
#pragma unroll
            for (int j = 0; j < 17; j++) o[20 + j] = a4[j];   // cols 40..73
        }
    }
}

// ---------------- launcher ----------------------------------------------------
extern "C" void kernel_launch(void* const* d_in, const int* in_sizes, int n_in,
                              void* d_out, int out_size) {
    const float* nf   = (const float*)d_in[0];
    const void*  ei   = d_in[1];
    const float* ea   = (const float*)d_in[2];
    const void*  srcn = d_in[3];
    const void*  dstn = d_in[4];
    const float* Ws1 = (const float*)d_in[5];
    const float* Wn1 = (const float*)d_in[6];
    const float* b1  = (const float*)d_in[7];
    const float* g1  = (const float*)d_in[8];
    const float* be1 = (const float*)d_in[9];
    const float* Ws2 = (const float*)d_in[10];
    const float* Wn2 = (const float*)d_in[11];
    const float* b2  = (const float*)d_in[12];
    const float* g2  = (const float*)d_in[13];
    const float* be2 = (const float*)d_in[14];
    const float* eW1 = (const float*)d_in[15];
    const float* eb1 = (const float*)d_in[16];
    const float* eW2 = (const float*)d_in[17];
    const float* eb2 = (const float*)d_in[18];
    const float* dW1 = (const float*)d_in[19];
    const float* db1 = (const float*)d_in[20];
    const float* dW2 = (const float*)d_in[21];
    const float* db2 = (const float*)d_in[22];

    float* out_recon = (float*)d_out;                                   // [1M, 74]
    float* out_er    = (float*)d_out + (long long)E_SC * EDGE_REPR;     // [1M, 74]

    const int smem_mlp = SM_TOTAL * sizeof(float);  // 56768 B
    cudaFuncSetAttribute(edge_mlp_kernel, cudaFuncAttributeMaxDynamicSharedMemorySize, smem_mlp);

    const int zero_total = N_NODES * IN_DIM + N_NODES + N_NODES * EMB;
    zero_kernel<<<(zero_total + 255) / 256, 256>>>();
    scatter1_kernel<<<(E_MSG + 255) / 256, 256>>>(ei, nf);
    sage1_kernel<<<N_NODES / 8, 256>>>(nf, Ws1, Wn1, b1, g1, be1, Wn2);
    scatter2_kernel<<<(E_MSG + 255) / 256, 256>>>(ei);
    sage2_kernel<<<N_NODES / 8, 256>>>(Ws2, b2, g2, be2);
    edge_mlp_kernel<<<(E_SC + EDGES_PER_BLOCK - 1) / EDGES_PER_BLOCK, MLP_THREADS, smem_mlp>>>(
        srcn, dstn, ea, eW1, eb1, eW2, eb2, dW1, db1, dW2, db2, out_recon, out_er);
}